// round 1
// baseline (speedup 1.0000x reference)
#include <cuda_runtime.h>
#include <math.h>

// Problem constants
namespace {
constexpr int Bb   = 2;
constexpr int Tt   = 2048;
constexpr int Dd   = 768;
constexpr int Hh   = 12;
constexpr int HDh  = 64;
constexpr int MROWS = Bb * Tt;     // 4096
constexpr int DFF   = 4 * Dd;      // 3072
constexpr int ATTN_SMEM = (4 * 64 * 65 + 64 * 16) * 4;  // 70656 bytes
}

// Scratch (no allocation allowed)
__device__ float g_xn [MROWS * Dd];
__device__ float g_q  [MROWS * Dd];
__device__ float g_k  [MROWS * Dd];
__device__ float g_v  [MROWS * Dd];
__device__ float g_ctx[MROWS * Dd];
__device__ float g_x1 [MROWS * Dd];
__device__ float g_h  [MROWS * DFF];

// ---------------------------------------------------------------------------
// LayerNorm: one block per row
// ---------------------------------------------------------------------------
__global__ __launch_bounds__(256) void ln_kernel(
    const float* __restrict__ x, const float* __restrict__ sc,
    const float* __restrict__ sh, float* __restrict__ out)
{
    const int row = blockIdx.x;
    const float* xr = x + (size_t)row * Dd;
    __shared__ float s1[256], s2[256];
    float a = 0.f, b = 0.f;
    for (int i = threadIdx.x; i < Dd; i += 256) {
        float v = xr[i];
        a += v; b += v * v;
    }
    s1[threadIdx.x] = a; s2[threadIdx.x] = b;
    __syncthreads();
    for (int off = 128; off > 0; off >>= 1) {
        if (threadIdx.x < off) {
            s1[threadIdx.x] += s1[threadIdx.x + off];
            s2[threadIdx.x] += s2[threadIdx.x + off];
        }
        __syncthreads();
    }
    const float mean = s1[0] * (1.f / Dd);
    const float var  = s2[0] * (1.f / Dd) - mean * mean;
    const float rstd = rsqrtf(var + 1e-5f);
    float* o = out + (size_t)row * Dd;
    for (int i = threadIdx.x; i < Dd; i += 256)
        o[i] = sc[i] * (xr[i] - mean) * rstd + sh[i];
}

// ---------------------------------------------------------------------------
// NT GEMM: C[M,N] = A[M,K] * B[N,K]^T (+ epilogue)
// EPI: 0 = none, 2 = +bias +residual, 3 = +bias, GELU
// 64x64 tile, BK=16, 256 threads, 4x4 per thread
// ---------------------------------------------------------------------------
template<int EPI>
__global__ __launch_bounds__(256) void gemm_nt(
    const float* __restrict__ A, const float* __restrict__ Bm,
    const float* __restrict__ bias, const float* __restrict__ res,
    float* __restrict__ C, int M, int N, int K)
{
    __shared__ __align__(16) float As[16][64];
    __shared__ __align__(16) float Bs[16][64];
    const int tid = threadIdx.x;
    const int ty = tid >> 4, tx = tid & 15;
    const int m0 = blockIdx.y * 64, n0 = blockIdx.x * 64;
    const int lrow = tid >> 2;
    const int lk   = (tid & 3) * 4;
    const float* Ap = A  + (size_t)(m0 + lrow) * K + lk;
    const float* Bp = Bm + (size_t)(n0 + lrow) * K + lk;

    float acc[4][4];
    #pragma unroll
    for (int i = 0; i < 4; i++)
        #pragma unroll
        for (int j = 0; j < 4; j++) acc[i][j] = 0.f;

    for (int k0 = 0; k0 < K; k0 += 16) {
        const float4 av = *(const float4*)(Ap + k0);
        const float4 bv = *(const float4*)(Bp + k0);
        __syncthreads();
        As[lk + 0][lrow] = av.x; As[lk + 1][lrow] = av.y;
        As[lk + 2][lrow] = av.z; As[lk + 3][lrow] = av.w;
        Bs[lk + 0][lrow] = bv.x; Bs[lk + 1][lrow] = bv.y;
        Bs[lk + 2][lrow] = bv.z; Bs[lk + 3][lrow] = bv.w;
        __syncthreads();
        #pragma unroll
        for (int k = 0; k < 16; k++) {
            const float4 a4 = *(const float4*)&As[k][ty * 4];
            const float4 b4 = *(const float4*)&Bs[k][tx * 4];
            const float a[4] = {a4.x, a4.y, a4.z, a4.w};
            const float b[4] = {b4.x, b4.y, b4.z, b4.w};
            #pragma unroll
            for (int i = 0; i < 4; i++)
                #pragma unroll
                for (int j = 0; j < 4; j++)
                    acc[i][j] += a[i] * b[j];
        }
    }

    #pragma unroll
    for (int i = 0; i < 4; i++) {
        const int m = m0 + ty * 4 + i;
        #pragma unroll
        for (int j = 0; j < 4; j++) {
            const int n = n0 + tx * 4 + j;
            float v = acc[i][j];
            if (EPI >= 2) v += bias[n];
            if (EPI == 2) v += res[(size_t)m * N + n];
            if (EPI == 3) {
                const float u = v;
                const float inner = 0.7978845608028654f * (u + 0.044715f * u * u * u);
                v = 0.5f * u * (1.f + tanhf(inner));
            }
            C[(size_t)m * N + n] = v;
        }
    }
}

// ---------------------------------------------------------------------------
// Causal flash attention (fp32). Grid: (T/64, H, B), 256 threads.
// Q/K/V layout: [b, t, h*64 + d] with row stride Dd.
// ---------------------------------------------------------------------------
__global__ __launch_bounds__(256) void attn_kernel(
    const float* __restrict__ Q, const float* __restrict__ K,
    const float* __restrict__ V, float* __restrict__ O)
{
    extern __shared__ float sm[];
    float* Qs  = sm;               // 64 x 65
    float* Ks  = Qs + 64 * 65;
    float* Vs  = Ks + 64 * 65;
    float* Ps  = Vs + 64 * 65;
    float* red = Ps + 64 * 65;     // 64 x 16

    const int qt = blockIdx.x, h = blockIdx.y, b = blockIdx.z;
    const int tid = threadIdx.x;
    const int ty4 = (tid >> 4) * 4, tx4 = (tid & 15) * 4;
    const int tx = tid & 15;
    const size_t base = ((size_t)b * Tt) * Dd + h * HDh;

    // Load Q tile (64 x 64)
    #pragma unroll
    for (int it = 0; it < 4; it++) {
        const int idx = tid + it * 256;
        const int r = idx >> 4, c = (idx & 15) * 4;
        const float4 qv = *(const float4*)(Q + base + (size_t)(qt * 64 + r) * Dd + c);
        Qs[r * 65 + c + 0] = qv.x; Qs[r * 65 + c + 1] = qv.y;
        Qs[r * 65 + c + 2] = qv.z; Qs[r * 65 + c + 3] = qv.w;
    }

    float acc[4][4];
    float mreg[4], lreg[4];
    #pragma unroll
    for (int i = 0; i < 4; i++) {
        mreg[i] = -INFINITY; lreg[i] = 0.f;
        #pragma unroll
        for (int j = 0; j < 4; j++) acc[i][j] = 0.f;
    }

    for (int kt = 0; kt <= qt; kt++) {
        __syncthreads();  // protect Ks/Vs/Ps reuse
        #pragma unroll
        for (int it = 0; it < 4; it++) {
            const int idx = tid + it * 256;
            const int r = idx >> 4, c = (idx & 15) * 4;
            const size_t goff = base + (size_t)(kt * 64 + r) * Dd + c;
            const float4 kv = *(const float4*)(K + goff);
            const float4 vv = *(const float4*)(V + goff);
            Ks[r * 65 + c + 0] = kv.x; Ks[r * 65 + c + 1] = kv.y;
            Ks[r * 65 + c + 2] = kv.z; Ks[r * 65 + c + 3] = kv.w;
            Vs[r * 65 + c + 0] = vv.x; Vs[r * 65 + c + 1] = vv.y;
            Vs[r * 65 + c + 2] = vv.z; Vs[r * 65 + c + 3] = vv.w;
        }
        __syncthreads();

        // S = Q K^T
        float s[4][4];
        #pragma unroll
        for (int i = 0; i < 4; i++)
            #pragma unroll
            for (int j = 0; j < 4; j++) s[i][j] = 0.f;
        #pragma unroll 8
        for (int k = 0; k < 64; k++) {
            float a[4], bb[4];
            #pragma unroll
            for (int i = 0; i < 4; i++) a[i]  = Qs[(ty4 + i) * 65 + k];
            #pragma unroll
            for (int j = 0; j < 4; j++) bb[j] = Ks[(tx4 + j) * 65 + k];
            #pragma unroll
            for (int i = 0; i < 4; i++)
                #pragma unroll
                for (int j = 0; j < 4; j++)
                    s[i][j] += a[i] * bb[j];
        }
        // scale + causal mask (only diagonal tile needs masking)
        #pragma unroll
        for (int i = 0; i < 4; i++)
            #pragma unroll
            for (int j = 0; j < 4; j++) {
                s[i][j] *= 0.125f;  // 1/sqrt(64)
                if (kt == qt && (tx4 + j) > (ty4 + i)) s[i][j] = -INFINITY;
            }

        // Row max (partial per thread -> red)
        #pragma unroll
        for (int i = 0; i < 4; i++) {
            float pm = fmaxf(fmaxf(s[i][0], s[i][1]), fmaxf(s[i][2], s[i][3]));
            red[(ty4 + i) * 16 + tx] = pm;
        }
        __syncthreads();
        float mnew[4], scl[4];
        #pragma unroll
        for (int i = 0; i < 4; i++) {
            const int r = ty4 + i;
            float mx = red[r * 16];
            #pragma unroll
            for (int t = 1; t < 16; t++) mx = fmaxf(mx, red[r * 16 + t]);
            mnew[i] = fmaxf(mreg[i], mx);
            scl[i]  = __expf(mreg[i] - mnew[i]);
        }
        __syncthreads();  // red about to be reused for sums
        #pragma unroll
        for (int i = 0; i < 4; i++) {
            float ps = 0.f;
            #pragma unroll
            for (int j = 0; j < 4; j++) {
                const float p = __expf(s[i][j] - mnew[i]);
                Ps[(ty4 + i) * 65 + tx4 + j] = p;
                ps += p;
            }
            red[(ty4 + i) * 16 + tx] = ps;
        }
        __syncthreads();
        #pragma unroll
        for (int i = 0; i < 4; i++) {
            const int r = ty4 + i;
            float ss = 0.f;
            #pragma unroll
            for (int t = 0; t < 16; t++) ss += red[r * 16 + t];
            lreg[i] = lreg[i] * scl[i] + ss;
            mreg[i] = mnew[i];
            #pragma unroll
            for (int j = 0; j < 4; j++) acc[i][j] *= scl[i];
        }

        // O += P * V
        #pragma unroll 8
        for (int k = 0; k < 64; k++) {
            float p[4], vv[4];
            #pragma unroll
            for (int i = 0; i < 4; i++) p[i]  = Ps[(ty4 + i) * 65 + k];
            #pragma unroll
            for (int j = 0; j < 4; j++) vv[j] = Vs[k * 65 + tx4 + j];
            #pragma unroll
            for (int i = 0; i < 4; i++)
                #pragma unroll
                for (int j = 0; j < 4; j++)
                    acc[i][j] += p[i] * vv[j];
        }
    }

    #pragma unroll
    for (int i = 0; i < 4; i++) {
        const float inv = 1.f / lreg[i];
        #pragma unroll
        for (int j = 0; j < 4; j++)
            O[base + (size_t)(qt * 64 + ty4 + i) * Dd + tx4 + j] = acc[i][j] * inv;
    }
}

// ---------------------------------------------------------------------------
// Launch
// ---------------------------------------------------------------------------
extern "C" void kernel_launch(void* const* d_in, const int* in_sizes, int n_in,
                              void* d_out, int out_size)
{
    const float* x    = (const float*)d_in[0];
    const float* ln1s = (const float*)d_in[1];
    const float* ln1b = (const float*)d_in[2];
    const float* wq   = (const float*)d_in[3];
    const float* wk   = (const float*)d_in[4];
    const float* wv   = (const float*)d_in[5];
    const float* wo   = (const float*)d_in[6];
    const float* bo   = (const float*)d_in[7];
    const float* ln2s = (const float*)d_in[8];
    const float* ln2b = (const float*)d_in[9];
    const float* w1   = (const float*)d_in[10];
    const float* b1   = (const float*)d_in[11];
    const float* w2   = (const float*)d_in[12];
    const float* b2   = (const float*)d_in[13];
    float* out = (float*)d_out;

    float *xn, *q, *k, *v, *ctx, *x1, *hbuf;
    cudaGetSymbolAddress((void**)&xn,   g_xn);
    cudaGetSymbolAddress((void**)&q,    g_q);
    cudaGetSymbolAddress((void**)&k,    g_k);
    cudaGetSymbolAddress((void**)&v,    g_v);
    cudaGetSymbolAddress((void**)&ctx,  g_ctx);
    cudaGetSymbolAddress((void**)&x1,   g_x1);
    cudaGetSymbolAddress((void**)&hbuf, g_h);

    cudaFuncSetAttribute(attn_kernel,
                         cudaFuncAttributeMaxDynamicSharedMemorySize, ATTN_SMEM);

    // LN1
    ln_kernel<<<MROWS, 256>>>(x, ln1s, ln1b, xn);

    // QKV projections
    dim3 gqkv(Dd / 64, MROWS / 64);
    gemm_nt<0><<<gqkv, 256>>>(xn, wq, nullptr, nullptr, q, MROWS, Dd, Dd);
    gemm_nt<0><<<gqkv, 256>>>(xn, wk, nullptr, nullptr, k, MROWS, Dd, Dd);
    gemm_nt<0><<<gqkv, 256>>>(xn, wv, nullptr, nullptr, v, MROWS, Dd, Dd);

    // Attention
    dim3 ga(Tt / 64, Hh, Bb);
    attn_kernel<<<ga, 256, ATTN_SMEM>>>(q, k, v, ctx);

    // Output projection + residual
    gemm_nt<2><<<gqkv, 256>>>(ctx, wo, bo, x, x1, MROWS, Dd, Dd);

    // LN2
    ln_kernel<<<MROWS, 256>>>(x1, ln2s, ln2b, xn);

    // MLP
    dim3 g1(DFF / 64, MROWS / 64);
    gemm_nt<3><<<g1, 256>>>(xn, w1, b1, nullptr, hbuf, MROWS, DFF, Dd);
    gemm_nt<2><<<gqkv, 256>>>(hbuf, w2, b2, x1, out, MROWS, Dd, DFF);
}

// round 5
// speedup vs baseline: 1.9555x; 1.9555x over previous
#include <cuda_runtime.h>
#include <cuda_bf16.h>
#include <math.h>
#include <cstdint>

// ---------------------------------------------------------------------------
// Problem constants
// ---------------------------------------------------------------------------
namespace {
constexpr int Bb   = 2;
constexpr int Tt   = 2048;
constexpr int Dd   = 768;
constexpr int Hh   = 12;
constexpr int HDh  = 64;
constexpr int MROWS = Bb * Tt;     // 4096
constexpr int DFF   = 4 * Dd;      // 3072
constexpr int ATTN_SMEM = (4 * 64 * 65 + 64 * 16) * 4;  // 70656 bytes

// mma.sync GEMM config: CTA tile 128x64, BK=32, 2-stage cp.async pipeline
constexpr int AP   = 56;             // padded row length (bf16 elems), 112B
constexpr int A_ST = 128 * AP;       // elems per A stage (7168)
constexpr int B_ST = 64 * AP;        // elems per B stage (3584)
constexpr int OFF_AH = 0;
constexpr int OFF_AL = 2 * A_ST;             // 14336
constexpr int OFF_BH = 4 * A_ST;             // 28672
constexpr int OFF_BL = 4 * A_ST + 2 * B_ST;  // 35840
constexpr int GSMEM_BYTES = (4 * A_ST + 4 * B_ST) * 2;  // 86016
}

// ---------------------------------------------------------------------------
// Scratch (no allocation allowed)
// ---------------------------------------------------------------------------
__device__ float g_q  [MROWS * Dd];
__device__ float g_k  [MROWS * Dd];
__device__ float g_v  [MROWS * Dd];
__device__ float g_ctx[MROWS * Dd];
__device__ float g_x1 [MROWS * Dd];

__device__ __nv_bfloat16 g_xn_h [MROWS * Dd], g_xn_l [MROWS * Dd];
__device__ __nv_bfloat16 g_ctx_h[MROWS * Dd], g_ctx_l[MROWS * Dd];
__device__ __nv_bfloat16 g_h_h  [MROWS * DFF], g_h_l [MROWS * DFF];
__device__ __nv_bfloat16 g_wq_h [Dd * Dd], g_wq_l [Dd * Dd];
__device__ __nv_bfloat16 g_wk_h [Dd * Dd], g_wk_l [Dd * Dd];
__device__ __nv_bfloat16 g_wv_h [Dd * Dd], g_wv_l [Dd * Dd];
__device__ __nv_bfloat16 g_wo_h [Dd * Dd], g_wo_l [Dd * Dd];
__device__ __nv_bfloat16 g_w1_h [DFF * Dd], g_w1_l [DFF * Dd];
__device__ __nv_bfloat16 g_w2_h [Dd * DFF], g_w2_l [Dd * DFF];

// ---------------------------------------------------------------------------
// PTX helpers (all baseline PTX: sm_80-era, compiles at compute_100)
// ---------------------------------------------------------------------------
__device__ __forceinline__ uint32_t smem_u32(const void* p) {
    uint32_t a;
    asm("{ .reg .u64 t; cvta.to.shared.u64 t, %1; cvt.u32.u64 %0, t; }"
        : "=r"(a) : "l"(p));
    return a;
}

__device__ __forceinline__ void cp16(uint32_t dst, const void* src) {
    asm volatile("cp.async.cg.shared.global [%0], [%1], 16;" :: "r"(dst), "l"(src));
}

__device__ __forceinline__ void ldm_x4(uint32_t* r, uint32_t addr) {
    asm volatile("ldmatrix.sync.aligned.m8n8.x4.shared.b16 {%0,%1,%2,%3}, [%4];"
        : "=r"(r[0]), "=r"(r[1]), "=r"(r[2]), "=r"(r[3]) : "r"(addr));
}

__device__ __forceinline__ void mma16816(float* c, const uint32_t* a, const uint32_t* b) {
    asm volatile(
        "mma.sync.aligned.m16n8k16.row.col.f32.bf16.bf16.f32 "
        "{%0,%1,%2,%3}, {%4,%5,%6,%7}, {%8,%9}, {%0,%1,%2,%3};"
        : "+f"(c[0]), "+f"(c[1]), "+f"(c[2]), "+f"(c[3])
        : "r"(a[0]), "r"(a[1]), "r"(a[2]), "r"(a[3]), "r"(b[0]), "r"(b[1]));
}

// ---------------------------------------------------------------------------
// LayerNorm -> (hi, lo) bf16 pair
// ---------------------------------------------------------------------------
__global__ __launch_bounds__(256) void ln_hilo(
    const float* __restrict__ x, const float* __restrict__ sc,
    const float* __restrict__ sh,
    __nv_bfloat16* __restrict__ oh, __nv_bfloat16* __restrict__ ol)
{
    const int row = blockIdx.x;
    const float* xr = x + (size_t)row * Dd;
    __shared__ float s1[256], s2[256];
    float a = 0.f, b = 0.f;
    for (int i = threadIdx.x; i < Dd; i += 256) {
        float v = xr[i];
        a += v; b += v * v;
    }
    s1[threadIdx.x] = a; s2[threadIdx.x] = b;
    __syncthreads();
    for (int off = 128; off > 0; off >>= 1) {
        if (threadIdx.x < off) {
            s1[threadIdx.x] += s1[threadIdx.x + off];
            s2[threadIdx.x] += s2[threadIdx.x + off];
        }
        __syncthreads();
    }
    const float mean = s1[0] * (1.f / Dd);
    const float var  = s2[0] * (1.f / Dd) - mean * mean;
    const float rstd = rsqrtf(var + 1e-5f);
    for (int i = threadIdx.x; i < Dd; i += 256) {
        const float v = sc[i] * (xr[i] - mean) * rstd + sh[i];
        const __nv_bfloat16 h = __float2bfloat16(v);
        oh[(size_t)row * Dd + i] = h;
        ol[(size_t)row * Dd + i] = __float2bfloat16(v - __bfloat162float(h));
    }
}

// fp32 -> (hi, lo) bf16
__global__ __launch_bounds__(256) void cvt_hilo(
    const float* __restrict__ in,
    __nv_bfloat16* __restrict__ oh, __nv_bfloat16* __restrict__ ol, int n)
{
    const int i = blockIdx.x * 256 + threadIdx.x;
    if (i < n) {
        const float v = in[i];
        const __nv_bfloat16 h = __float2bfloat16(v);
        oh[i] = h;
        ol[i] = __float2bfloat16(v - __bfloat162float(h));
    }
}

// ---------------------------------------------------------------------------
// HMMA split-bf16 NT GEMM: C[M,N] = A[M,K] * B[N,K]^T
// A ≈ Ah + Al, B ≈ Bh + Bl; D += AhBh + AhBl + AlBh (fp32 accum)
// EPI: 0 = fp32 out; 2 = +bias +res, fp32 out; 3 = +bias, GELU, (hi,lo) out
// CTA 128x64, BK=32, 256 thr = 8 warps (4m x 2n), warp tile 32x32
// ---------------------------------------------------------------------------
template<int EPI>
__global__ __launch_bounds__(256) void gemm_mma(
    const __nv_bfloat16* __restrict__ Ah, const __nv_bfloat16* __restrict__ Al,
    const __nv_bfloat16* __restrict__ Bh, const __nv_bfloat16* __restrict__ Bl,
    const float* __restrict__ bias, const float* __restrict__ res,
    float* __restrict__ Cf,
    __nv_bfloat16* __restrict__ Ch, __nv_bfloat16* __restrict__ Cl,
    int M, int N, int K)
{
    extern __shared__ __align__(16) char smem[];
    const uint32_t sb = smem_u32(smem);
    const int tid  = threadIdx.x;
    const int lane = tid & 31;
    const int w    = tid >> 5;
    const int wm   = w & 3;          // 0..3 (m)
    const int wn   = w >> 2;         // 0..1 (n)
    const int m0   = blockIdx.y * 128, n0 = blockIdx.x * 64;

    float acc[2][4][4];
    #pragma unroll
    for (int mi = 0; mi < 2; mi++)
        #pragma unroll
        for (int ni = 0; ni < 4; ni++)
            #pragma unroll
            for (int t = 0; t < 4; t++) acc[mi][ni][t] = 0.f;

    const int nc = K >> 5;  // chunks of 32

    // --- loader ---
    auto load_stage = [&](int st, int c) {
        const int k0 = c << 5;
        #pragma unroll
        for (int i = 0; i < 2; i++) {
            const int id  = tid + i * 256;        // 0..511
            const int row = id >> 2, seg = id & 3;
            const uint32_t d = (uint32_t)((st * A_ST + row * AP + seg * 8) * 2);
            const size_t g = (size_t)(m0 + row) * K + k0 + seg * 8;
            cp16(sb + OFF_AH * 2 + d, Ah + g);
            cp16(sb + OFF_AL * 2 + d, Al + g);
        }
        {
            const int row = tid >> 2, seg = tid & 3;   // 64 rows x 4 segs
            const uint32_t d = (uint32_t)((st * B_ST + row * AP + seg * 8) * 2);
            const size_t g = (size_t)(n0 + row) * K + k0 + seg * 8;
            cp16(sb + OFF_BH * 2 + d, Bh + g);
            cp16(sb + OFF_BL * 2 + d, Bl + g);
        }
    };

    load_stage(0, 0);
    asm volatile("cp.async.commit_group;");

    for (int c = 0; c < nc; c++) {
        if (c + 1 < nc) load_stage((c + 1) & 1, c + 1);
        asm volatile("cp.async.commit_group;");
        asm volatile("cp.async.wait_group 1;");
        __syncthreads();

        const int st = c & 1;
        #pragma unroll
        for (int ks = 0; ks < 2; ks++) {
            uint32_t ah[2][4], al[2][4];
            #pragma unroll
            for (int mi = 0; mi < 2; mi++) {
                const int row = wm * 32 + mi * 16 + (lane & 15);
                const int col = ks * 16 + (lane >> 4) * 8;
                const uint32_t off = (uint32_t)((st * A_ST + row * AP + col) * 2);
                ldm_x4(ah[mi], sb + OFF_AH * 2 + off);
                ldm_x4(al[mi], sb + OFF_AL * 2 + off);
            }
            uint32_t bh[4][2], bl[4][2];
            #pragma unroll
            for (int np = 0; np < 2; np++) {
                const int row = wn * 32 + np * 16 + ((lane >> 4) & 1) * 8 + (lane & 7);
                const int col = ks * 16 + ((lane >> 3) & 1) * 8;
                const uint32_t off = (uint32_t)((st * B_ST + row * AP + col) * 2);
                uint32_t r[4];
                ldm_x4(r, sb + OFF_BH * 2 + off);
                bh[np * 2][0] = r[0]; bh[np * 2][1] = r[1];
                bh[np * 2 + 1][0] = r[2]; bh[np * 2 + 1][1] = r[3];
                ldm_x4(r, sb + OFF_BL * 2 + off);
                bl[np * 2][0] = r[0]; bl[np * 2][1] = r[1];
                bl[np * 2 + 1][0] = r[2]; bl[np * 2 + 1][1] = r[3];
            }
            #pragma unroll
            for (int mi = 0; mi < 2; mi++)
                #pragma unroll
                for (int ni = 0; ni < 4; ni++) {
                    mma16816(acc[mi][ni], ah[mi], bh[ni]);
                    mma16816(acc[mi][ni], ah[mi], bl[ni]);
                    mma16816(acc[mi][ni], al[mi], bh[ni]);
                }
        }
        __syncthreads();
    }

    // --- epilogue ---
    const int rbase = m0 + wm * 32 + (lane >> 2);
    const int cbase = n0 + wn * 32 + (lane & 3) * 2;
    #pragma unroll
    for (int mi = 0; mi < 2; mi++) {
        #pragma unroll
        for (int ni = 0; ni < 4; ni++) {
            #pragma unroll
            for (int half = 0; half < 2; half++) {
                const int m = rbase + mi * 16 + half * 8;
                const int n = cbase + ni * 8;
                float v0 = acc[mi][ni][half * 2];
                float v1 = acc[mi][ni][half * 2 + 1];
                const size_t o = (size_t)m * N + n;
                if (EPI == 0) {
                    float2 t = {v0, v1};
                    *(float2*)(Cf + o) = t;
                } else if (EPI == 2) {
                    const float2 r2 = *(const float2*)(res + o);
                    float2 t = {v0 + bias[n] + r2.x, v1 + bias[n + 1] + r2.y};
                    *(float2*)(Cf + o) = t;
                } else {  // EPI == 3
                    float u0 = v0 + bias[n];
                    float u1 = v1 + bias[n + 1];
                    const float i0 = 0.7978845608028654f * (u0 + 0.044715f * u0 * u0 * u0);
                    const float i1 = 0.7978845608028654f * (u1 + 0.044715f * u1 * u1 * u1);
                    const float g0 = 0.5f * u0 * (1.f + tanhf(i0));
                    const float g1 = 0.5f * u1 * (1.f + tanhf(i1));
                    const __nv_bfloat16 h0 = __float2bfloat16(g0);
                    const __nv_bfloat16 h1 = __float2bfloat16(g1);
                    __nv_bfloat162 hp, lp;
                    hp.x = h0; hp.y = h1;
                    lp.x = __float2bfloat16(g0 - __bfloat162float(h0));
                    lp.y = __float2bfloat16(g1 - __bfloat162float(h1));
                    *(__nv_bfloat162*)(Ch + o) = hp;
                    *(__nv_bfloat162*)(Cl + o) = lp;
                }
            }
        }
    }
}

// ---------------------------------------------------------------------------
// Causal flash attention (fp32), unchanged.
// ---------------------------------------------------------------------------
__global__ __launch_bounds__(256) void attn_kernel(
    const float* __restrict__ Q, const float* __restrict__ K,
    const float* __restrict__ V, float* __restrict__ O)
{
    extern __shared__ float sm[];
    float* Qs  = sm;               // 64 x 65
    float* Ks  = Qs + 64 * 65;
    float* Vs  = Ks + 64 * 65;
    float* Ps  = Vs + 64 * 65;
    float* red = Ps + 64 * 65;     // 64 x 16

    const int qt = blockIdx.x, h = blockIdx.y, b = blockIdx.z;
    const int tid = threadIdx.x;
    const int ty4 = (tid >> 4) * 4, tx4 = (tid & 15) * 4;
    const int tx = tid & 15;
    const size_t base = ((size_t)b * Tt) * Dd + h * HDh;

    #pragma unroll
    for (int it = 0; it < 4; it++) {
        const int idx = tid + it * 256;
        const int r = idx >> 4, c = (idx & 15) * 4;
        const float4 qv = *(const float4*)(Q + base + (size_t)(qt * 64 + r) * Dd + c);
        Qs[r * 65 + c + 0] = qv.x; Qs[r * 65 + c + 1] = qv.y;
        Qs[r * 65 + c + 2] = qv.z; Qs[r * 65 + c + 3] = qv.w;
    }

    float acc[4][4];
    float mreg[4], lreg[4];
    #pragma unroll
    for (int i = 0; i < 4; i++) {
        mreg[i] = -INFINITY; lreg[i] = 0.f;
        #pragma unroll
        for (int j = 0; j < 4; j++) acc[i][j] = 0.f;
    }

    for (int kt = 0; kt <= qt; kt++) {
        __syncthreads();
        #pragma unroll
        for (int it = 0; it < 4; it++) {
            const int idx = tid + it * 256;
            const int r = idx >> 4, c = (idx & 15) * 4;
            const size_t goff = base + (size_t)(kt * 64 + r) * Dd + c;
            const float4 kv = *(const float4*)(K + goff);
            const float4 vv = *(const float4*)(V + goff);
            Ks[r * 65 + c + 0] = kv.x; Ks[r * 65 + c + 1] = kv.y;
            Ks[r * 65 + c + 2] = kv.z; Ks[r * 65 + c + 3] = kv.w;
            Vs[r * 65 + c + 0] = vv.x; Vs[r * 65 + c + 1] = vv.y;
            Vs[r * 65 + c + 2] = vv.z; Vs[r * 65 + c + 3] = vv.w;
        }
        __syncthreads();

        float s[4][4];
        #pragma unroll
        for (int i = 0; i < 4; i++)
            #pragma unroll
            for (int j = 0; j < 4; j++) s[i][j] = 0.f;
        #pragma unroll 8
        for (int k = 0; k < 64; k++) {
            float a[4], bb[4];
            #pragma unroll
            for (int i = 0; i < 4; i++) a[i]  = Qs[(ty4 + i) * 65 + k];
            #pragma unroll
            for (int j = 0; j < 4; j++) bb[j] = Ks[(tx4 + j) * 65 + k];
            #pragma unroll
            for (int i = 0; i < 4; i++)
                #pragma unroll
                for (int j = 0; j < 4; j++)
                    s[i][j] += a[i] * bb[j];
        }
        #pragma unroll
        for (int i = 0; i < 4; i++)
            #pragma unroll
            for (int j = 0; j < 4; j++) {
                s[i][j] *= 0.125f;
                if (kt == qt && (tx4 + j) > (ty4 + i)) s[i][j] = -INFINITY;
            }

        #pragma unroll
        for (int i = 0; i < 4; i++) {
            float pm = fmaxf(fmaxf(s[i][0], s[i][1]), fmaxf(s[i][2], s[i][3]));
            red[(ty4 + i) * 16 + tx] = pm;
        }
        __syncthreads();
        float mnew[4], scl[4];
        #pragma unroll
        for (int i = 0; i < 4; i++) {
            const int r = ty4 + i;
            float mx = red[r * 16];
            #pragma unroll
            for (int t = 1; t < 16; t++) mx = fmaxf(mx, red[r * 16 + t]);
            mnew[i] = fmaxf(mreg[i], mx);
            scl[i]  = __expf(mreg[i] - mnew[i]);
        }
        __syncthreads();
        #pragma unroll
        for (int i = 0; i < 4; i++) {
            float ps = 0.f;
            #pragma unroll
            for (int j = 0; j < 4; j++) {
                const float p = __expf(s[i][j] - mnew[i]);
                Ps[(ty4 + i) * 65 + tx4 + j] = p;
                ps += p;
            }
            red[(ty4 + i) * 16 + tx] = ps;
        }
        __syncthreads();
        #pragma unroll
        for (int i = 0; i < 4; i++) {
            const int r = ty4 + i;
            float ss = 0.f;
            #pragma unroll
            for (int t = 0; t < 16; t++) ss += red[r * 16 + t];
            lreg[i] = lreg[i] * scl[i] + ss;
            mreg[i] = mnew[i];
            #pragma unroll
            for (int j = 0; j < 4; j++) acc[i][j] *= scl[i];
        }

        #pragma unroll 8
        for (int k = 0; k < 64; k++) {
            float p[4], vv[4];
            #pragma unroll
            for (int i = 0; i < 4; i++) p[i]  = Ps[(ty4 + i) * 65 + k];
            #pragma unroll
            for (int j = 0; j < 4; j++) vv[j] = Vs[k * 65 + tx4 + j];
            #pragma unroll
            for (int i = 0; i < 4; i++)
                #pragma unroll
                for (int j = 0; j < 4; j++)
                    acc[i][j] += p[i] * vv[j];
        }
    }

    #pragma unroll
    for (int i = 0; i < 4; i++) {
        const float inv = 1.f / lreg[i];
        #pragma unroll
        for (int j = 0; j < 4; j++)
            O[base + (size_t)(qt * 64 + ty4 + i) * Dd + tx4 + j] = acc[i][j] * inv;
    }
}

// ---------------------------------------------------------------------------
// Launch
// ---------------------------------------------------------------------------
extern "C" void kernel_launch(void* const* d_in, const int* in_sizes, int n_in,
                              void* d_out, int out_size)
{
    const float* x    = (const float*)d_in[0];
    const float* ln1s = (const float*)d_in[1];
    const float* ln1b = (const float*)d_in[2];
    const float* wq   = (const float*)d_in[3];
    const float* wk   = (const float*)d_in[4];
    const float* wv   = (const float*)d_in[5];
    const float* wo   = (const float*)d_in[6];
    const float* bo   = (const float*)d_in[7];
    const float* ln2s = (const float*)d_in[8];
    const float* ln2b = (const float*)d_in[9];
    const float* w1   = (const float*)d_in[10];
    const float* b1   = (const float*)d_in[11];
    const float* w2   = (const float*)d_in[12];
    const float* b2   = (const float*)d_in[13];
    float* out = (float*)d_out;

    float *q, *k, *v, *ctx, *x1;
    cudaGetSymbolAddress((void**)&q,   g_q);
    cudaGetSymbolAddress((void**)&k,   g_k);
    cudaGetSymbolAddress((void**)&v,   g_v);
    cudaGetSymbolAddress((void**)&ctx, g_ctx);
    cudaGetSymbolAddress((void**)&x1,  g_x1);

    __nv_bfloat16 *xnh, *xnl, *ctxh, *ctxl, *hh, *hl;
    __nv_bfloat16 *wqh, *wql, *wkh, *wkl, *wvh, *wvl, *woh, *wol;
    __nv_bfloat16 *w1h, *w1l, *w2h, *w2l;
    cudaGetSymbolAddress((void**)&xnh,  g_xn_h);
    cudaGetSymbolAddress((void**)&xnl,  g_xn_l);
    cudaGetSymbolAddress((void**)&ctxh, g_ctx_h);
    cudaGetSymbolAddress((void**)&ctxl, g_ctx_l);
    cudaGetSymbolAddress((void**)&hh,   g_h_h);
    cudaGetSymbolAddress((void**)&hl,   g_h_l);
    cudaGetSymbolAddress((void**)&wqh,  g_wq_h);
    cudaGetSymbolAddress((void**)&wql,  g_wq_l);
    cudaGetSymbolAddress((void**)&wkh,  g_wk_h);
    cudaGetSymbolAddress((void**)&wkl,  g_wk_l);
    cudaGetSymbolAddress((void**)&wvh,  g_wv_h);
    cudaGetSymbolAddress((void**)&wvl,  g_wv_l);
    cudaGetSymbolAddress((void**)&woh,  g_wo_h);
    cudaGetSymbolAddress((void**)&wol,  g_wo_l);
    cudaGetSymbolAddress((void**)&w1h,  g_w1_h);
    cudaGetSymbolAddress((void**)&w1l,  g_w1_l);
    cudaGetSymbolAddress((void**)&w2h,  g_w2_h);
    cudaGetSymbolAddress((void**)&w2l,  g_w2_l);

    cudaFuncSetAttribute(attn_kernel,
                         cudaFuncAttributeMaxDynamicSharedMemorySize, ATTN_SMEM);
    cudaFuncSetAttribute(gemm_mma<0>,
                         cudaFuncAttributeMaxDynamicSharedMemorySize, GSMEM_BYTES);
    cudaFuncSetAttribute(gemm_mma<2>,
                         cudaFuncAttributeMaxDynamicSharedMemorySize, GSMEM_BYTES);
    cudaFuncSetAttribute(gemm_mma<3>,
                         cudaFuncAttributeMaxDynamicSharedMemorySize, GSMEM_BYTES);

    // Weight conversions (hi/lo split)
    const int NDD = Dd * Dd, NW1 = DFF * Dd;
    cvt_hilo<<<(NDD + 255) / 256, 256>>>(wq, wqh, wql, NDD);
    cvt_hilo<<<(NDD + 255) / 256, 256>>>(wk, wkh, wkl, NDD);
    cvt_hilo<<<(NDD + 255) / 256, 256>>>(wv, wvh, wvl, NDD);
    cvt_hilo<<<(NDD + 255) / 256, 256>>>(wo, woh, wol, NDD);
    cvt_hilo<<<(NW1 + 255) / 256, 256>>>(w1, w1h, w1l, NW1);
    cvt_hilo<<<(NW1 + 255) / 256, 256>>>(w2, w2h, w2l, NW1);

    // LN1 -> xn (hi/lo)
    ln_hilo<<<MROWS, 256>>>(x, ln1s, ln1b, xnh, xnl);

    // QKV projections (fp32 out)
    dim3 gdd(Dd / 64, MROWS / 128);
    gemm_mma<0><<<gdd, 256, GSMEM_BYTES>>>(xnh, xnl, wqh, wql, nullptr, nullptr,
                                           q, nullptr, nullptr, MROWS, Dd, Dd);
    gemm_mma<0><<<gdd, 256, GSMEM_BYTES>>>(xnh, xnl, wkh, wkl, nullptr, nullptr,
                                           k, nullptr, nullptr, MROWS, Dd, Dd);
    gemm_mma<0><<<gdd, 256, GSMEM_BYTES>>>(xnh, xnl, wvh, wvl, nullptr, nullptr,
                                           v, nullptr, nullptr, MROWS, Dd, Dd);

    // Attention
    dim3 ga(Tt / 64, Hh, Bb);
    attn_kernel<<<ga, 256, ATTN_SMEM>>>(q, k, v, ctx);

    // ctx -> hi/lo
    const int NX = MROWS * Dd;
    cvt_hilo<<<(NX + 255) / 256, 256>>>(ctx, ctxh, ctxl, NX);

    // O projection + bias + residual -> x1 (fp32)
    gemm_mma<2><<<gdd, 256, GSMEM_BYTES>>>(ctxh, ctxl, woh, wol, bo, x,
                                           x1, nullptr, nullptr, MROWS, Dd, Dd);

    // LN2 -> xn (hi/lo)
    ln_hilo<<<MROWS, 256>>>(x1, ln2s, ln2b, xnh, xnl);

    // MLP1: bias + GELU -> h (hi/lo bf16)
    dim3 g1(DFF / 64, MROWS / 128);
    gemm_mma<3><<<g1, 256, GSMEM_BYTES>>>(xnh, xnl, w1h, w1l, b1, nullptr,
                                          nullptr, hh, hl, MROWS, DFF, Dd);

    // MLP2: bias + residual -> out (fp32)
    gemm_mma<2><<<gdd, 256, GSMEM_BYTES>>>(hh, hl, w2h, w2l, b2, x1,
                                           out, nullptr, nullptr, MROWS, Dd, DFF);
}

// round 7
// speedup vs baseline: 2.9850x; 1.5264x over previous
#include <cuda_runtime.h>
#include <cuda_bf16.h>
#include <math.h>
#include <cstdint>

// ---------------------------------------------------------------------------
// Problem constants
// ---------------------------------------------------------------------------
namespace {
constexpr int Bb   = 2;
constexpr int Tt   = 2048;
constexpr int Dd   = 768;
constexpr int QKV3 = 3 * Dd;       // 2304
constexpr int Hh   = 12;
constexpr int MROWS = Bb * Tt;     // 4096
constexpr int DFF   = 4 * Dd;      // 3072

// mma.sync GEMM config: CTA tile 128x64, BK=32, 2-stage cp.async pipeline
constexpr int AP   = 56;             // padded row length (bf16 elems), 112B
constexpr int A_ST = 128 * AP;
constexpr int B_ST = 64 * AP;
constexpr int OFF_AH = 0;
constexpr int OFF_AL = 2 * A_ST;
constexpr int OFF_BH = 4 * A_ST;
constexpr int OFF_BL = 4 * A_ST + 2 * B_ST;
constexpr int GSMEM_BYTES = (4 * A_ST + 4 * B_ST) * 2;  // 86016

// attention smem: 2 stages x (Kh,Kl,Vh,Vl) 64x72 bf16 tiles
constexpr int APAD = 72;
constexpr int ATILE = 64 * APAD;        // 4608 elems
constexpr int ASTG  = 4 * ATILE;        // 18432 elems per stage
constexpr int ATTN_SMEM2 = 2 * ASTG * 2;  // 73728 bytes
}

// ---------------------------------------------------------------------------
// Scratch (no allocation allowed)
// ---------------------------------------------------------------------------
__device__ float g_x1 [MROWS * Dd];

__device__ __nv_bfloat16 g_xn_h  [MROWS * Dd],  g_xn_l  [MROWS * Dd];
__device__ __nv_bfloat16 g_qkv_h [MROWS * QKV3], g_qkv_l[MROWS * QKV3];
__device__ __nv_bfloat16 g_ctx_h [MROWS * Dd],  g_ctx_l [MROWS * Dd];
__device__ __nv_bfloat16 g_h_h   [MROWS * DFF], g_h_l   [MROWS * DFF];
__device__ __nv_bfloat16 g_wqkv_h[QKV3 * Dd],   g_wqkv_l[QKV3 * Dd];
__device__ __nv_bfloat16 g_wo_h  [Dd * Dd],     g_wo_l  [Dd * Dd];
__device__ __nv_bfloat16 g_w1_h  [DFF * Dd],    g_w1_l  [DFF * Dd];
__device__ __nv_bfloat16 g_w2_h  [Dd * DFF],    g_w2_l  [Dd * DFF];

// ---------------------------------------------------------------------------
// PTX helpers (baseline PTX, legal at compute_100)
// ---------------------------------------------------------------------------
__device__ __forceinline__ uint32_t smem_u32(const void* p) {
    uint32_t a;
    asm("{ .reg .u64 t; cvta.to.shared.u64 t, %1; cvt.u32.u64 %0, t; }"
        : "=r"(a) : "l"(p));
    return a;
}

__device__ __forceinline__ void cp16(uint32_t dst, const void* src) {
    asm volatile("cp.async.cg.shared.global [%0], [%1], 16;" :: "r"(dst), "l"(src));
}

__device__ __forceinline__ void ldm_x4(uint32_t* r, uint32_t addr) {
    asm volatile("ldmatrix.sync.aligned.m8n8.x4.shared.b16 {%0,%1,%2,%3}, [%4];"
        : "=r"(r[0]), "=r"(r[1]), "=r"(r[2]), "=r"(r[3]) : "r"(addr));
}

__device__ __forceinline__ void ldm_x4_t(uint32_t* r, uint32_t addr) {
    asm volatile("ldmatrix.sync.aligned.m8n8.x4.trans.shared.b16 {%0,%1,%2,%3}, [%4];"
        : "=r"(r[0]), "=r"(r[1]), "=r"(r[2]), "=r"(r[3]) : "r"(addr));
}

__device__ __forceinline__ void mma16816(float* c, const uint32_t* a, const uint32_t* b) {
    asm volatile(
        "mma.sync.aligned.m16n8k16.row.col.f32.bf16.bf16.f32 "
        "{%0,%1,%2,%3}, {%4,%5,%6,%7}, {%8,%9}, {%0,%1,%2,%3};"
        : "+f"(c[0]), "+f"(c[1]), "+f"(c[2]), "+f"(c[3])
        : "r"(a[0]), "r"(a[1]), "r"(a[2]), "r"(a[3]), "r"(b[0]), "r"(b[1]));
}

// pack two floats to bf16x2 (lo = first arg)
__device__ __forceinline__ uint32_t packbf(float lo, float hi) {
    uint32_t r;
    asm("cvt.rn.bf16x2.f32 %0, %1, %2;" : "=r"(r) : "f"(hi), "f"(lo));
    return r;
}

// ---------------------------------------------------------------------------
// LayerNorm -> (hi, lo) bf16 pair
// ---------------------------------------------------------------------------
__global__ __launch_bounds__(256) void ln_hilo(
    const float* __restrict__ x, const float* __restrict__ sc,
    const float* __restrict__ sh,
    __nv_bfloat16* __restrict__ oh, __nv_bfloat16* __restrict__ ol)
{
    const int row = blockIdx.x;
    const float* xr = x + (size_t)row * Dd;
    __shared__ float s1[256], s2[256];
    float a = 0.f, b = 0.f;
    for (int i = threadIdx.x; i < Dd; i += 256) {
        float v = xr[i];
        a += v; b += v * v;
    }
    s1[threadIdx.x] = a; s2[threadIdx.x] = b;
    __syncthreads();
    for (int off = 128; off > 0; off >>= 1) {
        if (threadIdx.x < off) {
            s1[threadIdx.x] += s1[threadIdx.x + off];
            s2[threadIdx.x] += s2[threadIdx.x + off];
        }
        __syncthreads();
    }
    const float mean = s1[0] * (1.f / Dd);
    const float var  = s2[0] * (1.f / Dd) - mean * mean;
    const float rstd = rsqrtf(var + 1e-5f);
    for (int i = threadIdx.x; i < Dd; i += 256) {
        const float v = sc[i] * (xr[i] - mean) * rstd + sh[i];
        const __nv_bfloat16 h = __float2bfloat16(v);
        oh[(size_t)row * Dd + i] = h;
        ol[(size_t)row * Dd + i] = __float2bfloat16(v - __bfloat162float(h));
    }
}

// fp32 -> (hi, lo) bf16
__global__ __launch_bounds__(256) void cvt_hilo(
    const float* __restrict__ in,
    __nv_bfloat16* __restrict__ oh, __nv_bfloat16* __restrict__ ol, int n)
{
    const int i = blockIdx.x * 256 + threadIdx.x;
    if (i < n) {
        const float v = in[i];
        const __nv_bfloat16 h = __float2bfloat16(v);
        oh[i] = h;
        ol[i] = __float2bfloat16(v - __bfloat162float(h));
    }
}

// ---------------------------------------------------------------------------
// HMMA split-bf16 NT GEMM: C[M,N] = A[M,K] * B[N,K]^T
// EPI: 1 = (hi,lo) bf16 out, no bias; 2 = +bias +res, fp32 out;
//      3 = +bias, GELU, (hi,lo) out
// CTA 128x64, BK=32, 256 thr = 8 warps (4m x 2n), warp tile 32x32
// ---------------------------------------------------------------------------
template<int EPI>
__global__ __launch_bounds__(256) void gemm_mma(
    const __nv_bfloat16* __restrict__ Ah, const __nv_bfloat16* __restrict__ Al,
    const __nv_bfloat16* __restrict__ Bh, const __nv_bfloat16* __restrict__ Bl,
    const float* __restrict__ bias, const float* __restrict__ res,
    float* __restrict__ Cf,
    __nv_bfloat16* __restrict__ Ch, __nv_bfloat16* __restrict__ Cl,
    int M, int N, int K)
{
    extern __shared__ __align__(16) char smem[];
    const uint32_t sb = smem_u32(smem);
    const int tid  = threadIdx.x;
    const int lane = tid & 31;
    const int w    = tid >> 5;
    const int wm   = w & 3;
    const int wn   = w >> 2;
    const int m0   = blockIdx.y * 128, n0 = blockIdx.x * 64;

    float acc[2][4][4];
    #pragma unroll
    for (int mi = 0; mi < 2; mi++)
        #pragma unroll
        for (int ni = 0; ni < 4; ni++)
            #pragma unroll
            for (int t = 0; t < 4; t++) acc[mi][ni][t] = 0.f;

    const int nc = K >> 5;

    auto load_stage = [&](int st, int c) {
        const int k0 = c << 5;
        #pragma unroll
        for (int i = 0; i < 2; i++) {
            const int id  = tid + i * 256;
            const int row = id >> 2, seg = id & 3;
            const uint32_t d = (uint32_t)((st * A_ST + row * AP + seg * 8) * 2);
            const size_t g = (size_t)(m0 + row) * K + k0 + seg * 8;
            cp16(sb + OFF_AH * 2 + d, Ah + g);
            cp16(sb + OFF_AL * 2 + d, Al + g);
        }
        {
            const int row = tid >> 2, seg = tid & 3;
            const uint32_t d = (uint32_t)((st * B_ST + row * AP + seg * 8) * 2);
            const size_t g = (size_t)(n0 + row) * K + k0 + seg * 8;
            cp16(sb + OFF_BH * 2 + d, Bh + g);
            cp16(sb + OFF_BL * 2 + d, Bl + g);
        }
    };

    load_stage(0, 0);
    asm volatile("cp.async.commit_group;");

    for (int c = 0; c < nc; c++) {
        if (c + 1 < nc) load_stage((c + 1) & 1, c + 1);
        asm volatile("cp.async.commit_group;");
        asm volatile("cp.async.wait_group 1;");
        __syncthreads();

        const int st = c & 1;
        #pragma unroll
        for (int ks = 0; ks < 2; ks++) {
            uint32_t ah[2][4], al[2][4];
            #pragma unroll
            for (int mi = 0; mi < 2; mi++) {
                const int row = wm * 32 + mi * 16 + (lane & 15);
                const int col = ks * 16 + (lane >> 4) * 8;
                const uint32_t off = (uint32_t)((st * A_ST + row * AP + col) * 2);
                ldm_x4(ah[mi], sb + OFF_AH * 2 + off);
                ldm_x4(al[mi], sb + OFF_AL * 2 + off);
            }
            uint32_t bh[4][2], bl[4][2];
            #pragma unroll
            for (int np = 0; np < 2; np++) {
                const int row = wn * 32 + np * 16 + ((lane >> 4) & 1) * 8 + (lane & 7);
                const int col = ks * 16 + ((lane >> 3) & 1) * 8;
                const uint32_t off = (uint32_t)((st * B_ST + row * AP + col) * 2);
                uint32_t r[4];
                ldm_x4(r, sb + OFF_BH * 2 + off);
                bh[np * 2][0] = r[0]; bh[np * 2][1] = r[1];
                bh[np * 2 + 1][0] = r[2]; bh[np * 2 + 1][1] = r[3];
                ldm_x4(r, sb + OFF_BL * 2 + off);
                bl[np * 2][0] = r[0]; bl[np * 2][1] = r[1];
                bl[np * 2 + 1][0] = r[2]; bl[np * 2 + 1][1] = r[3];
            }
            #pragma unroll
            for (int mi = 0; mi < 2; mi++)
                #pragma unroll
                for (int ni = 0; ni < 4; ni++) {
                    mma16816(acc[mi][ni], ah[mi], bh[ni]);
                    mma16816(acc[mi][ni], ah[mi], bl[ni]);
                    mma16816(acc[mi][ni], al[mi], bh[ni]);
                }
        }
        __syncthreads();
    }

    // --- epilogue ---
    const int rbase = m0 + wm * 32 + (lane >> 2);
    const int cbase = n0 + wn * 32 + (lane & 3) * 2;
    #pragma unroll
    for (int mi = 0; mi < 2; mi++) {
        #pragma unroll
        for (int ni = 0; ni < 4; ni++) {
            #pragma unroll
            for (int half = 0; half < 2; half++) {
                const int m = rbase + mi * 16 + half * 8;
                const int n = cbase + ni * 8;
                float v0 = acc[mi][ni][half * 2];
                float v1 = acc[mi][ni][half * 2 + 1];
                const size_t o = (size_t)m * N + n;
                if (EPI == 1) {
                    const __nv_bfloat16 h0 = __float2bfloat16(v0);
                    const __nv_bfloat16 h1 = __float2bfloat16(v1);
                    __nv_bfloat162 hp, lp;
                    hp.x = h0; hp.y = h1;
                    lp.x = __float2bfloat16(v0 - __bfloat162float(h0));
                    lp.y = __float2bfloat16(v1 - __bfloat162float(h1));
                    *(__nv_bfloat162*)(Ch + o) = hp;
                    *(__nv_bfloat162*)(Cl + o) = lp;
                } else if (EPI == 2) {
                    const float2 r2 = *(const float2*)(res + o);
                    float2 t = {v0 + bias[n] + r2.x, v1 + bias[n + 1] + r2.y};
                    *(float2*)(Cf + o) = t;
                } else {  // EPI == 3
                    float u0 = v0 + bias[n];
                    float u1 = v1 + bias[n + 1];
                    const float i0 = 0.7978845608028654f * (u0 + 0.044715f * u0 * u0 * u0);
                    const float i1 = 0.7978845608028654f * (u1 + 0.044715f * u1 * u1 * u1);
                    const float g0 = 0.5f * u0 * (1.f + tanhf(i0));
                    const float g1 = 0.5f * u1 * (1.f + tanhf(i1));
                    const __nv_bfloat16 h0 = __float2bfloat16(g0);
                    const __nv_bfloat16 h1 = __float2bfloat16(g1);
                    __nv_bfloat162 hp, lp;
                    hp.x = h0; hp.y = h1;
                    lp.x = __float2bfloat16(g0 - __bfloat162float(h0));
                    lp.y = __float2bfloat16(g1 - __bfloat162float(h1));
                    *(__nv_bfloat162*)(Ch + o) = hp;
                    *(__nv_bfloat162*)(Cl + o) = lp;
                }
            }
        }
    }
}

// ---------------------------------------------------------------------------
// HMMA split-bf16 causal flash attention.
// Grid (32, 12, 2), 128 threads. qkv layout: [row = b*T + t][q|k|v of 768 each],
// head cols h*64..h*64+63. Output ctx (hi,lo) bf16 [row][768].
// ---------------------------------------------------------------------------
__global__ __launch_bounds__(128) void attn_mma(
    const __nv_bfloat16* __restrict__ qkvh, const __nv_bfloat16* __restrict__ qkvl,
    __nv_bfloat16* __restrict__ ch, __nv_bfloat16* __restrict__ cl)
{
    extern __shared__ __align__(16) char smem[];
    const uint32_t sb = smem_u32(smem);
    const int tid = threadIdx.x, lane = tid & 31, w = tid >> 5;
    const int qt = (int)gridDim.x - 1 - (int)blockIdx.x;   // heavy tiles first
    const int h = blockIdx.y, b = blockIdx.z;
    const int wq0 = w * 16;
    const int colb = h * 64;

    // ---- stage Q into stage0 K area, extract fragments ----
    {
        const int rbase = b * Tt + qt * 64;
        #pragma unroll
        for (int i = 0; i < 4; i++) {
            const int t2 = tid + i * 128;
            const int row = t2 >> 3, seg = (t2 & 7) * 8;
            const size_t src = (size_t)(rbase + row) * QKV3 + colb + seg;
            const uint32_t dst = sb + (uint32_t)((row * APAD + seg) * 2);
            cp16(dst,             qkvh + src);
            cp16(dst + ATILE * 2, qkvl + src);
        }
    }
    asm volatile("cp.async.commit_group;");
    asm volatile("cp.async.wait_group 0;");
    __syncthreads();

    uint32_t qh[4][4], ql[4][4];
    #pragma unroll
    for (int ks = 0; ks < 4; ks++) {
        const int row = wq0 + (lane & 15);
        const int col = ks * 16 + (lane >> 4) * 8;
        const uint32_t a = sb + (uint32_t)((row * APAD + col) * 2);
        ldm_x4(qh[ks], a);
        ldm_x4(ql[ks], a + ATILE * 2);
    }
    __syncthreads();

    auto load_kv = [&](int st, int kt) {
        const int rbase = b * Tt + kt * 64;
        #pragma unroll
        for (int i = 0; i < 4; i++) {
            const int t2 = tid + i * 128;
            const int row = t2 >> 3, seg = (t2 & 7) * 8;
            const size_t srcK = (size_t)(rbase + row) * QKV3 + Dd + colb + seg;
            const uint32_t dst = sb + (uint32_t)((st * ASTG + row * APAD + seg) * 2);
            cp16(dst,             qkvh + srcK);        // Kh
            cp16(dst + ATILE * 2, qkvl + srcK);        // Kl
            cp16(dst + ATILE * 4, qkvh + srcK + Dd);   // Vh
            cp16(dst + ATILE * 6, qkvl + srcK + Dd);   // Vl
        }
    };

    float oacc[8][4];
    #pragma unroll
    for (int i = 0; i < 8; i++)
        #pragma unroll
        for (int t = 0; t < 4; t++) oacc[i][t] = 0.f;
    float m0 = -1e30f, m1 = -1e30f, l0 = 0.f, l1 = 0.f;

    load_kv(0, 0);
    asm volatile("cp.async.commit_group;");

    const int r0 = lane >> 2, c0 = (lane & 3) * 2;

    for (int kt = 0; kt <= qt; kt++) {
        if (kt < qt) load_kv((kt + 1) & 1, kt + 1);
        asm volatile("cp.async.commit_group;");
        asm volatile("cp.async.wait_group 1;");
        __syncthreads();
        const uint32_t stb = sb + (uint32_t)((kt & 1) * ASTG * 2);

        // ---- S = Q K^T (split bf16) ----
        float sacc[8][4];
        #pragma unroll
        for (int i = 0; i < 8; i++)
            #pragma unroll
            for (int t = 0; t < 4; t++) sacc[i][t] = 0.f;

        #pragma unroll
        for (int ks = 0; ks < 4; ks++) {
            #pragma unroll
            for (int np = 0; np < 4; np++) {
                const int row = np * 16 + ((lane >> 4) & 1) * 8 + (lane & 7);
                const int col = ks * 16 + ((lane >> 3) & 1) * 8;
                const uint32_t a = stb + (uint32_t)((row * APAD + col) * 2);
                uint32_t rh[4], rl[4];
                ldm_x4(rh, a);
                ldm_x4(rl, a + ATILE * 2);
                uint32_t bh0[2] = {rh[0], rh[1]}, bh1[2] = {rh[2], rh[3]};
                uint32_t bl0[2] = {rl[0], rl[1]}, bl1[2] = {rl[2], rl[3]};
                mma16816(sacc[np * 2],     qh[ks], bh0);
                mma16816(sacc[np * 2],     qh[ks], bl0);
                mma16816(sacc[np * 2],     ql[ks], bh0);
                mma16816(sacc[np * 2 + 1], qh[ks], bh1);
                mma16816(sacc[np * 2 + 1], qh[ks], bl1);
                mma16816(sacc[np * 2 + 1], ql[ks], bh1);
            }
        }

        // ---- scale + causal mask ----
        const bool diag = (kt == qt);
        #pragma unroll
        for (int nt = 0; nt < 8; nt++) {
            #pragma unroll
            for (int e = 0; e < 4; e++) {
                float sv = sacc[nt][e] * 0.125f;
                if (diag) {
                    const int rr = wq0 + r0 + ((e >> 1) << 3);
                    const int cc = nt * 8 + c0 + (e & 1);
                    if (cc > rr) sv = -1e30f;
                }
                sacc[nt][e] = sv;
            }
        }

        // ---- online softmax (row stats via quad shfl) ----
        float mx0 = -1e30f, mx1 = -1e30f;
        #pragma unroll
        for (int nt = 0; nt < 8; nt++) {
            mx0 = fmaxf(mx0, fmaxf(sacc[nt][0], sacc[nt][1]));
            mx1 = fmaxf(mx1, fmaxf(sacc[nt][2], sacc[nt][3]));
        }
        mx0 = fmaxf(mx0, __shfl_xor_sync(0xffffffffu, mx0, 1));
        mx0 = fmaxf(mx0, __shfl_xor_sync(0xffffffffu, mx0, 2));
        mx1 = fmaxf(mx1, __shfl_xor_sync(0xffffffffu, mx1, 1));
        mx1 = fmaxf(mx1, __shfl_xor_sync(0xffffffffu, mx1, 2));
        const float mn0 = fmaxf(m0, mx0), mn1 = fmaxf(m1, mx1);
        const float sc0 = __expf(m0 - mn0), sc1 = __expf(m1 - mn1);
        m0 = mn0; m1 = mn1;

        uint32_t ph[4][4], pl[4][4];
        float s0 = 0.f, s1 = 0.f;
        #pragma unroll
        for (int nt = 0; nt < 8; nt++) {
            const float p0 = __expf(sacc[nt][0] - mn0);
            const float p1 = __expf(sacc[nt][1] - mn0);
            const float p2 = __expf(sacc[nt][2] - mn1);
            const float p3 = __expf(sacc[nt][3] - mn1);
            s0 += p0 + p1; s1 += p2 + p3;
            const float h0 = __bfloat162float(__float2bfloat16(p0));
            const float h1 = __bfloat162float(__float2bfloat16(p1));
            const float h2 = __bfloat162float(__float2bfloat16(p2));
            const float h3 = __bfloat162float(__float2bfloat16(p3));
            const int ks2 = nt >> 1, hf = (nt & 1) * 2;
            ph[ks2][hf]     = packbf(h0, h1);
            ph[ks2][hf + 1] = packbf(h2, h3);
            pl[ks2][hf]     = packbf(p0 - h0, p1 - h1);
            pl[ks2][hf + 1] = packbf(p2 - h2, p3 - h3);
        }
        s0 += __shfl_xor_sync(0xffffffffu, s0, 1);
        s0 += __shfl_xor_sync(0xffffffffu, s0, 2);
        s1 += __shfl_xor_sync(0xffffffffu, s1, 1);
        s1 += __shfl_xor_sync(0xffffffffu, s1, 2);
        l0 = l0 * sc0 + s0;
        l1 = l1 * sc1 + s1;

        #pragma unroll
        for (int dt = 0; dt < 8; dt++) {
            oacc[dt][0] *= sc0; oacc[dt][1] *= sc0;
            oacc[dt][2] *= sc1; oacc[dt][3] *= sc1;
        }

        // ---- O += P V (split bf16, V via trans ldmatrix) ----
        const uint32_t vtb = stb + ATILE * 4;
        #pragma unroll
        for (int ks = 0; ks < 4; ks++) {
            #pragma unroll
            for (int dp = 0; dp < 4; dp++) {
                const int krow = 16 * ks + (lane & 15);
                const int ncol = dp * 16 + (lane >> 4) * 8;
                const uint32_t a = vtb + (uint32_t)((krow * APAD + ncol) * 2);
                uint32_t rh[4], rl[4];
                ldm_x4_t(rh, a);
                ldm_x4_t(rl, a + ATILE * 2);
                uint32_t vh0[2] = {rh[0], rh[1]}, vh1[2] = {rh[2], rh[3]};
                uint32_t vl0[2] = {rl[0], rl[1]}, vl1[2] = {rl[2], rl[3]};
                mma16816(oacc[dp * 2],     ph[ks], vh0);
                mma16816(oacc[dp * 2],     ph[ks], vl0);
                mma16816(oacc[dp * 2],     pl[ks], vh0);
                mma16816(oacc[dp * 2 + 1], ph[ks], vh1);
                mma16816(oacc[dp * 2 + 1], ph[ks], vl1);
                mma16816(oacc[dp * 2 + 1], pl[ks], vh1);
            }
        }
        __syncthreads();
    }

    // ---- epilogue: normalize, write ctx (hi,lo) ----
    const float inv0 = 1.f / l0, inv1 = 1.f / l1;
    const size_t rg0 = (size_t)(b * Tt + qt * 64 + wq0 + r0);
    #pragma unroll
    for (int dt = 0; dt < 8; dt++) {
        const int col = colb + dt * 8 + c0;
        {
            const float v0 = oacc[dt][0] * inv0, v1 = oacc[dt][1] * inv0;
            const __nv_bfloat16 h0 = __float2bfloat16(v0);
            const __nv_bfloat16 h1 = __float2bfloat16(v1);
            __nv_bfloat162 hp, lp;
            hp.x = h0; hp.y = h1;
            lp.x = __float2bfloat16(v0 - __bfloat162float(h0));
            lp.y = __float2bfloat16(v1 - __bfloat162float(h1));
            *(__nv_bfloat162*)(ch + rg0 * Dd + col) = hp;
            *(__nv_bfloat162*)(cl + rg0 * Dd + col) = lp;
        }
        {
            const float v0 = oacc[dt][2] * inv1, v1 = oacc[dt][3] * inv1;
            const __nv_bfloat16 h0 = __float2bfloat16(v0);
            const __nv_bfloat16 h1 = __float2bfloat16(v1);
            __nv_bfloat162 hp, lp;
            hp.x = h0; hp.y = h1;
            lp.x = __float2bfloat16(v0 - __bfloat162float(h0));
            lp.y = __float2bfloat16(v1 - __bfloat162float(h1));
            *(__nv_bfloat162*)(ch + (rg0 + 8) * Dd + col) = hp;
            *(__nv_bfloat162*)(cl + (rg0 + 8) * Dd + col) = lp;
        }
    }
}

// ---------------------------------------------------------------------------
// Launch
// ---------------------------------------------------------------------------
extern "C" void kernel_launch(void* const* d_in, const int* in_sizes, int n_in,
                              void* d_out, int out_size)
{
    const float* x    = (const float*)d_in[0];
    const float* ln1s = (const float*)d_in[1];
    const float* ln1b = (const float*)d_in[2];
    const float* wq   = (const float*)d_in[3];
    const float* wk   = (const float*)d_in[4];
    const float* wv   = (const float*)d_in[5];
    const float* wo   = (const float*)d_in[6];
    const float* bo   = (const float*)d_in[7];
    const float* ln2s = (const float*)d_in[8];
    const float* ln2b = (const float*)d_in[9];
    const float* w1   = (const float*)d_in[10];
    const float* b1   = (const float*)d_in[11];
    const float* w2   = (const float*)d_in[12];
    const float* b2   = (const float*)d_in[13];
    float* out = (float*)d_out;

    float* x1;
    cudaGetSymbolAddress((void**)&x1, g_x1);

    __nv_bfloat16 *xnh, *xnl, *qkvh, *qkvl, *ctxh, *ctxl, *hh, *hl;
    __nv_bfloat16 *wqkvh, *wqkvl, *woh, *wol, *w1h, *w1l, *w2h, *w2l;
    cudaGetSymbolAddress((void**)&xnh,   g_xn_h);
    cudaGetSymbolAddress((void**)&xnl,   g_xn_l);
    cudaGetSymbolAddress((void**)&qkvh,  g_qkv_h);
    cudaGetSymbolAddress((void**)&qkvl,  g_qkv_l);
    cudaGetSymbolAddress((void**)&ctxh,  g_ctx_h);
    cudaGetSymbolAddress((void**)&ctxl,  g_ctx_l);
    cudaGetSymbolAddress((void**)&hh,    g_h_h);
    cudaGetSymbolAddress((void**)&hl,    g_h_l);
    cudaGetSymbolAddress((void**)&wqkvh, g_wqkv_h);
    cudaGetSymbolAddress((void**)&wqkvl, g_wqkv_l);
    cudaGetSymbolAddress((void**)&woh,   g_wo_h);
    cudaGetSymbolAddress((void**)&wol,   g_wo_l);
    cudaGetSymbolAddress((void**)&w1h,   g_w1_h);
    cudaGetSymbolAddress((void**)&w1l,   g_w1_l);
    cudaGetSymbolAddress((void**)&w2h,   g_w2_h);
    cudaGetSymbolAddress((void**)&w2l,   g_w2_l);

    cudaFuncSetAttribute(attn_mma,
                         cudaFuncAttributeMaxDynamicSharedMemorySize, ATTN_SMEM2);
    cudaFuncSetAttribute(gemm_mma<1>,
                         cudaFuncAttributeMaxDynamicSharedMemorySize, GSMEM_BYTES);
    cudaFuncSetAttribute(gemm_mma<2>,
                         cudaFuncAttributeMaxDynamicSharedMemorySize, GSMEM_BYTES);
    cudaFuncSetAttribute(gemm_mma<3>,
                         cudaFuncAttributeMaxDynamicSharedMemorySize, GSMEM_BYTES);

    // Weight conversions (hi/lo split); wq/wk/wv stacked along N
    const int NDD = Dd * Dd, NW1 = DFF * Dd;
    cvt_hilo<<<(NDD + 255) / 256, 256>>>(wq, wqkvh,           wqkvl,           NDD);
    cvt_hilo<<<(NDD + 255) / 256, 256>>>(wk, wqkvh + NDD,     wqkvl + NDD,     NDD);
    cvt_hilo<<<(NDD + 255) / 256, 256>>>(wv, wqkvh + 2 * NDD, wqkvl + 2 * NDD, NDD);
    cvt_hilo<<<(NDD + 255) / 256, 256>>>(wo, woh, wol, NDD);
    cvt_hilo<<<(NW1 + 255) / 256, 256>>>(w1, w1h, w1l, NW1);
    cvt_hilo<<<(NW1 + 255) / 256, 256>>>(w2, w2h, w2l, NW1);

    // LN1 -> xn (hi/lo)
    ln_hilo<<<MROWS, 256>>>(x, ln1s, ln1b, xnh, xnl);

    // Fused QKV projection -> qkv (hi/lo bf16), N = 2304
    dim3 gqkv(QKV3 / 64, MROWS / 128);
    gemm_mma<1><<<gqkv, 256, GSMEM_BYTES>>>(xnh, xnl, wqkvh, wqkvl,
                                            nullptr, nullptr, nullptr,
                                            qkvh, qkvl, MROWS, QKV3, Dd);

    // Attention (HMMA flash) -> ctx (hi/lo bf16)
    dim3 ga(Tt / 64, Hh, Bb);
    attn_mma<<<ga, 128, ATTN_SMEM2>>>(qkvh, qkvl, ctxh, ctxl);

    // O projection + bias + residual -> x1 (fp32)
    dim3 gdd(Dd / 64, MROWS / 128);
    gemm_mma<2><<<gdd, 256, GSMEM_BYTES>>>(ctxh, ctxl, woh, wol, bo, x,
                                           x1, nullptr, nullptr, MROWS, Dd, Dd);

    // LN2 -> xn (hi/lo)
    ln_hilo<<<MROWS, 256>>>(x1, ln2s, ln2b, xnh, xnl);

    // MLP1: bias + GELU -> h (hi/lo bf16)
    dim3 g1(DFF / 64, MROWS / 128);
    gemm_mma<3><<<g1, 256, GSMEM_BYTES>>>(xnh, xnl, w1h, w1l, b1, nullptr,
                                          nullptr, hh, hl, MROWS, DFF, Dd);

    // MLP2: bias + residual -> out (fp32)
    gemm_mma<2><<<gdd, 256, GSMEM_BYTES>>>(hh, hl, w2h, w2l, b2, x1,
                                           out, nullptr, nullptr, MROWS, Dd, DFF);
}